// round 11
// baseline (speedup 1.0000x reference)
#include <cuda_runtime.h>
#include <stdint.h>

// Shapes (fixed):
//   x:        (B, M, N)  float32          B=32, M=512, N=128
//   location: (B, M, 2)  int64/int32 (y, x), H=W=128
//   out:      (B, N, H, W) float32
#define BB   32
#define MM   512
#define NN   128
#define WPX  128
#define HWPX 16384   // 128*128
#define HW4  4096    // HWPX/4
#define NCH  32      // channels per block (8 q-iterations)
#define PPB  1024    // pixels per block (256 threads x 4)

// ---------------------------------------------------------------------------
// Single fused kernel (R10 structure, NCH 16->32): block = (pixel range of
// 1024, 32-channel group, batch). Grid 2048 still offers 13.8 blocks/SM at
// the 8-block occupancy cap (R10 body = 32 regs), so the chip stays full
// while Phase-A replication halves (4x instead of 8x): 8 MB instead of
// 16 MB of redundant location reads, half the smem-init/barrier overhead.
//
// Phase A: build 2 KB smem inverse map for this block's 1024-pixel range by
//          scanning batch b's 512 locations (2 per thread, L2-resident).
//          int64-vs-int32 layout detected via __syncthreads_and on odd int32
//          words (all-zero <=> int64; under int32 these are x coords
//          ~U[0,128), P(all 256 zero) ~ 2^-1792).
// Phase B: per q: 4 predicated LDG.128 (one per entity slot), register
//          transpose, 4 streaming STG.128 (warp = 512B bursts). Only 4
//          float4s live -> fits the 32-reg budget of (256,8) = 100% occ cap.
__global__ void __launch_bounds__(256, 8) fused_scatter_kernel(
        const float4* __restrict__ xin,
        const int*    __restrict__ loc32,
        float4*       __restrict__ out) {
    __shared__ short s_inv[PPB];

    const int t  = threadIdx.x;
    const int b  = blockIdx.z;
    const int n0 = blockIdx.y * NCH;
    const int p0 = blockIdx.x * PPB;          // first pixel of this block

    // --- Phase A: smem inverse map ----------------------------------------
    ((int*)s_inv)[2 * t]     = -1;            // 4 shorts = -1 per thread
    ((int*)s_inv)[2 * t + 1] = -1;

    const int* locb32 = loc32 + b * MM * 2;   // int32 view of batch b
    const int* locb64 = loc32 + b * MM * 4;   // int64 view (int32 pairs)

    // layout probe (doubles as the barrier ordering smem init vs scatter):
    int is64 = __syncthreads_and(loc32[2 * t + 1] == 0);

    #pragma unroll
    for (int k = 0; k < 2; k++) {
        int e = t + 256 * k;                  // entity m in [0, 512)
        int y, x;
        if (is64) { y = locb64[4 * e]; x = locb64[4 * e + 2]; }
        else      { y = locb32[2 * e]; x = locb32[2 * e + 1]; }
        int rel = y * WPX + x - p0;
        if ((unsigned)rel < PPB) s_inv[rel] = (short)e;
    }
    __syncthreads();

    // --- Phase B: pipelined gather + zero-fill (R4/R10 body, 8 q-iters) ---
    short4 iv = ((const short4*)s_inv)[t];
    int m0 = iv.x, m1 = iv.y, m2 = iv.z, m3 = iv.w;
    bool v0 = m0 >= 0, v1 = m1 >= 0, v2 = m2 >= 0, v3 = m3 >= 0;
    int i0 = m0 * (NN / 4), i1 = m1 * (NN / 4);
    int i2 = m2 * (NN / 4), i3 = m3 * (NN / 4);

    // x[b][m][n0 + 0..31] = 8 float4s at row stride NN/4 = 32.
    const float4* xb = xin + b * (MM * NN / 4) + (n0 >> 2);
    float4*       o  = out + (b * NN + n0) * HW4 + (p0 >> 2) + t;
    const float4  z  = make_float4(0.f, 0.f, 0.f, 0.f);

    #pragma unroll
    for (int q = 0; q < NCH / 4; q++) {
        float4 a = v0 ? __ldg(xb + i0 + q) : z;
        float4 c = v1 ? __ldg(xb + i1 + q) : z;
        float4 d = v2 ? __ldg(xb + i2 + q) : z;
        float4 f = v3 ? __ldg(xb + i3 + q) : z;

        __stcs(o + (4 * q + 0) * HW4, make_float4(a.x, c.x, d.x, f.x));
        __stcs(o + (4 * q + 1) * HW4, make_float4(a.y, c.y, d.y, f.y));
        __stcs(o + (4 * q + 2) * HW4, make_float4(a.z, c.z, d.z, f.z));
        __stcs(o + (4 * q + 3) * HW4, make_float4(a.w, c.w, d.w, f.w));
    }
}

// ---------------------------------------------------------------------------
extern "C" void kernel_launch(void* const* d_in, const int* in_sizes, int n_in,
                              void* d_out, int out_size) {
    const float* x     = (const float*)d_in[0];
    const int*   loc32 = (const int*)d_in[1];
    float*       out   = (float*)d_out;
    (void)in_sizes; (void)n_in; (void)out_size;

    // One launch: (16 pixel-ranges, 4 channel-groups, 32 batches) x 256 thr.
    fused_scatter_kernel<<<dim3(HWPX / PPB, NN / NCH, BB), 256>>>(
        (const float4*)x, loc32, (float4*)out);
}

// round 12
// speedup vs baseline: 1.0453x; 1.0453x over previous
#include <cuda_runtime.h>
#include <stdint.h>

// Shapes (fixed):
//   x:        (B, M, N)  float32          B=32, M=512, N=128
//   location: (B, M, 2)  int64/int32 (y, x), H=W=128
//   out:      (B, N, H, W) float32
#define BB   32
#define MM   512
#define NN   128
#define WPX  128
#define HWPX 16384   // 128*128
#define HW4  4096    // HWPX/4
#define NCH  16      // channels per block
#define PPB  1024    // pixels per block (256 threads x 4)

// ---------------------------------------------------------------------------
// Single fused kernel (R10 configuration — best measured: 45.06 us, 5.9 TB/s
// effective write stream). Block = (pixel range of 1024, 16-channel chunk,
// batch); grid 4096 = 3.46 waves at the 8-block/SM occupancy cap (32 regs),
// which the R7/R8/R11 grid-scaling experiments showed is required to keep
// the store stream saturated (2048 -> 1.73 waves loses ~2 us to the tail).
//
// Phase A: build 2 KB smem inverse map for this block's 1024-pixel range by
//          scanning batch b's 512 locations (2 per thread, L2-resident).
//          int64-vs-int32 layout detected via __syncthreads_and on odd int32
//          words (all-zero <=> int64; under int32 these are x coords
//          ~U[0,128), P(all 256 zero) ~ 2^-1792).
// Phase B: per q: 4 predicated LDG.128 (one per entity slot), register
//          transpose, 4 streaming STG.128 (warp = 512B bursts). Only 4
//          float4s live -> 32 regs under __launch_bounds__(256, 8).
__global__ void __launch_bounds__(256, 8) fused_scatter_kernel(
        const float4* __restrict__ xin,
        const int*    __restrict__ loc32,
        float4*       __restrict__ out) {
    __shared__ short s_inv[PPB];

    const int t  = threadIdx.x;
    const int b  = blockIdx.z;
    const int n0 = blockIdx.y * NCH;
    const int p0 = blockIdx.x * PPB;          // first pixel of this block

    // --- Phase A: smem inverse map ----------------------------------------
    ((int*)s_inv)[2 * t]     = -1;            // 4 shorts = -1 per thread
    ((int*)s_inv)[2 * t + 1] = -1;

    const int* locb32 = loc32 + b * MM * 2;   // int32 view of batch b
    const int* locb64 = loc32 + b * MM * 4;   // int64 view (int32 pairs)

    // layout probe (doubles as the barrier ordering smem init vs scatter):
    int is64 = __syncthreads_and(loc32[2 * t + 1] == 0);

    #pragma unroll
    for (int k = 0; k < 2; k++) {
        int e = t + 256 * k;                  // entity m in [0, 512)
        int y, x;
        if (is64) { y = locb64[4 * e]; x = locb64[4 * e + 2]; }
        else      { y = locb32[2 * e]; x = locb32[2 * e + 1]; }
        int rel = y * WPX + x - p0;
        if ((unsigned)rel < PPB) s_inv[rel] = (short)e;
    }
    __syncthreads();

    // --- Phase B: pipelined gather + zero-fill ----------------------------
    short4 iv = ((const short4*)s_inv)[t];
    int m0 = iv.x, m1 = iv.y, m2 = iv.z, m3 = iv.w;
    bool v0 = m0 >= 0, v1 = m1 >= 0, v2 = m2 >= 0, v3 = m3 >= 0;
    int i0 = m0 * (NN / 4), i1 = m1 * (NN / 4);
    int i2 = m2 * (NN / 4), i3 = m3 * (NN / 4);

    // x[b][m][n0 + 0..15] = 4 float4s at row stride NN/4 = 32.
    const float4* xb = xin + b * (MM * NN / 4) + (n0 >> 2);
    float4*       o  = out + (b * NN + n0) * HW4 + (p0 >> 2) + t;
    const float4  z  = make_float4(0.f, 0.f, 0.f, 0.f);

    #pragma unroll
    for (int q = 0; q < 4; q++) {
        float4 a = v0 ? __ldg(xb + i0 + q) : z;
        float4 c = v1 ? __ldg(xb + i1 + q) : z;
        float4 d = v2 ? __ldg(xb + i2 + q) : z;
        float4 f = v3 ? __ldg(xb + i3 + q) : z;

        __stcs(o + (4 * q + 0) * HW4, make_float4(a.x, c.x, d.x, f.x));
        __stcs(o + (4 * q + 1) * HW4, make_float4(a.y, c.y, d.y, f.y));
        __stcs(o + (4 * q + 2) * HW4, make_float4(a.z, c.z, d.z, f.z));
        __stcs(o + (4 * q + 3) * HW4, make_float4(a.w, c.w, d.w, f.w));
    }
}

// ---------------------------------------------------------------------------
extern "C" void kernel_launch(void* const* d_in, const int* in_sizes, int n_in,
                              void* d_out, int out_size) {
    const float* x     = (const float*)d_in[0];
    const int*   loc32 = (const int*)d_in[1];
    float*       out   = (float*)d_out;
    (void)in_sizes; (void)n_in; (void)out_size;

    // One launch: (16 pixel-ranges, 8 channel-chunks, 32 batches) x 256 thr.
    fused_scatter_kernel<<<dim3(HWPX / PPB, NN / NCH, BB), 256>>>(
        (const float4*)x, loc32, (float4*)out);
}

// round 13
// speedup vs baseline: 1.0483x; 1.0028x over previous
#include <cuda_runtime.h>
#include <stdint.h>

// Shapes (fixed):
//   x:        (B, M, N)  float32          B=32, M=512, N=128
//   location: (B, M, 2)  int64/int32 (y, x), H=W=128
//   out:      (B, N, H, W) float32
#define BB   32
#define MM   512
#define NN   128
#define WPX  128
#define HWPX 16384   // 128*128
#define HW4  4096    // HWPX/4
#define NCH  16      // channels per block
#define TPB  512     // threads per block
#define PPB  2048    // pixels per block (512 threads x 4)

// ---------------------------------------------------------------------------
// R10 body, widened blocks: 512 threads / 2048 pixels. Grid = 8 x 8 x 32 =
// 2048 blocks at the 4-block/SM cap (launch_bounds 512,4; 2048 thr/SM same
// as R10) -> wave count stays 3.46 (R11's failure mode was halving waves;
// here concurrent blocks halve WITH the grid). Phase-A replication halves:
// each smem inverse map now serves 2048 pixels (8 MB total location reads
// instead of 16 MB, one location per thread, half the barriers chip-wide).
//
// Phase A: build 4 KB smem inverse map for this block's 2048-pixel range by
//          scanning batch b's 512 locations (1 per thread, L2-resident).
//          int64-vs-int32 layout detected via __syncthreads_and on odd int32
//          words (all-zero <=> int64; under int32 these are x coords
//          ~U[0,128), P(all 512 zero) ~ 2^-3584).
// Phase B: per q: 4 predicated LDG.128 (one per entity slot), register
//          transpose, 4 streaming STG.128 (warp = 512B bursts). Only 4
//          float4s live -> 32 regs.
__global__ void __launch_bounds__(TPB, 4) fused_scatter_kernel(
        const float4* __restrict__ xin,
        const int*    __restrict__ loc32,
        float4*       __restrict__ out) {
    __shared__ short s_inv[PPB];

    const int t  = threadIdx.x;
    const int b  = blockIdx.z;
    const int n0 = blockIdx.y * NCH;
    const int p0 = blockIdx.x * PPB;          // first pixel of this block

    // --- Phase A: smem inverse map ----------------------------------------
    ((int*)s_inv)[2 * t]     = -1;            // 4 shorts = -1 per thread
    ((int*)s_inv)[2 * t + 1] = -1;

    const int* locb32 = loc32 + b * MM * 2;   // int32 view of batch b
    const int* locb64 = loc32 + b * MM * 4;   // int64 view (int32 pairs)

    // layout probe (doubles as the barrier ordering smem init vs scatter):
    int is64 = __syncthreads_and(loc32[2 * t + 1] == 0);

    {
        int e = t;                            // entity m in [0, 512)
        int y, x;
        if (is64) { y = locb64[4 * e]; x = locb64[4 * e + 2]; }
        else      { y = locb32[2 * e]; x = locb32[2 * e + 1]; }
        int rel = y * WPX + x - p0;
        if ((unsigned)rel < PPB) s_inv[rel] = (short)e;
    }
    __syncthreads();

    // --- Phase B: pipelined gather + zero-fill (R10 body, unchanged) ------
    short4 iv = ((const short4*)s_inv)[t];
    int m0 = iv.x, m1 = iv.y, m2 = iv.z, m3 = iv.w;
    bool v0 = m0 >= 0, v1 = m1 >= 0, v2 = m2 >= 0, v3 = m3 >= 0;
    int i0 = m0 * (NN / 4), i1 = m1 * (NN / 4);
    int i2 = m2 * (NN / 4), i3 = m3 * (NN / 4);

    // x[b][m][n0 + 0..15] = 4 float4s at row stride NN/4 = 32.
    const float4* xb = xin + b * (MM * NN / 4) + (n0 >> 2);
    float4*       o  = out + (b * NN + n0) * HW4 + (p0 >> 2) + t;
    const float4  z  = make_float4(0.f, 0.f, 0.f, 0.f);

    #pragma unroll
    for (int q = 0; q < 4; q++) {
        float4 a = v0 ? __ldg(xb + i0 + q) : z;
        float4 c = v1 ? __ldg(xb + i1 + q) : z;
        float4 d = v2 ? __ldg(xb + i2 + q) : z;
        float4 f = v3 ? __ldg(xb + i3 + q) : z;

        __stcs(o + (4 * q + 0) * HW4, make_float4(a.x, c.x, d.x, f.x));
        __stcs(o + (4 * q + 1) * HW4, make_float4(a.y, c.y, d.y, f.y));
        __stcs(o + (4 * q + 2) * HW4, make_float4(a.z, c.z, d.z, f.z));
        __stcs(o + (4 * q + 3) * HW4, make_float4(a.w, c.w, d.w, f.w));
    }
}

// ---------------------------------------------------------------------------
extern "C" void kernel_launch(void* const* d_in, const int* in_sizes, int n_in,
                              void* d_out, int out_size) {
    const float* x     = (const float*)d_in[0];
    const int*   loc32 = (const int*)d_in[1];
    float*       out   = (float*)d_out;
    (void)in_sizes; (void)n_in; (void)out_size;

    // One launch: (8 pixel-ranges, 8 channel-chunks, 32 batches) x 512 thr.
    fused_scatter_kernel<<<dim3(HWPX / PPB, NN / NCH, BB), TPB>>>(
        (const float4*)x, loc32, (float4*)out);
}